// round 4
// baseline (speedup 1.0000x reference)
#include <cuda_runtime.h>

// ---------------------------------------------------------------------------
// ComputeLoss (YOLOv5-style), fixed shapes:
//   p0: (32,255,80,80)  p1: (32,255,40,40)  p2: (32,255,20,20)
//   targets: (1024,6) = [img, cls, cx, cy, w, h]
// Output: one float32 scalar.
//
// SINGLE kernel:
//   blocks [0, OBJ_BLOCKS)      : dense sum of softplus(obj_logit) (3.2 MB stream)
//   blocks [OBJ_BLOCKS, GRID)   : one warp per candidate; GIoU/lbox, lcls,
//                                 telescoping atomicMax correction for lobj
//   last block to finish        : finalizes scalar, zeroes the touched
//                                 g_objmax cells (compacted list), resets state
// ---------------------------------------------------------------------------

#define NIMG 32
#define NA   3
#define NCLS 80
#define MT   1024
#define CPL  (5*NA*MT)            // 15360 candidates per level
#define TOTC (3*CPL)              // 46080
#define CELLS0 (NIMG*NA*80*80)    // 614400
#define CELLS1 (NIMG*NA*40*40)    // 153600
#define CELLS2 (NIMG*NA*20*20)    // 38400
#define CELLS_TOT (CELLS0+CELLS1+CELLS2)   // 806400

#define OBJ_GROUPS (CELLS_TOT/4)              // 201600 float4 groups
#define OBJ_BLOCKS ((OBJ_GROUPS + 255)/256)   // 788
#define CAND_BLOCKS (TOTC/8)                  // 5760
#define GRID (OBJ_BLOCKS + CAND_BLOCKS)       // 6548

__constant__ float c_anch[3][3][2] = {
  {{1.25f,1.625f},{2.0f,3.75f},{4.125f,2.875f}},
  {{1.875f,3.8125f},{3.875f,2.8125f},{3.6875f,7.4375f}},
  {{3.625f,2.8125f},{4.875f,6.1875f},{11.65625f,10.1875f}}
};

// per-cell objectness max (float bits >= 0). Zero at module load; the last
// block zeroes every touched cell each launch (list-driven).
__device__ unsigned g_objmax[CELLS_TOT];
__device__ int   g_cellList[TOTC];
__device__ int   g_nflag;
__device__ int   g_done;
// [0..2]=lbox, [3..5]=cls, [6..8]=obj_softplus, [9..11]=obj_corr
__device__ double g_acc[12];
__device__ int g_cnt[3];

__device__ __forceinline__ float sp_(float x){          // softplus (fast-math)
    return fmaxf(x, 0.f) + __logf(1.f + __expf(-fabsf(x)));
}
__device__ __forceinline__ float sig_(float x){
    return 1.f / (1.f + __expf(-x));
}

__device__ __forceinline__ float giou_(float px,float py,float pw,float ph,
                                       float gx,float gy,float gw,float gh){
    const float eps = 1e-7f;
    float px1 = px - pw*0.5f, py1 = py - ph*0.5f;
    float px2 = px + pw*0.5f, py2 = py + ph*0.5f;
    float qx1 = gx - gw*0.5f, qy1 = gy - gh*0.5f;
    float qx2 = gx + gw*0.5f, qy2 = gy + gh*0.5f;
    float iw = fmaxf(fminf(px2,qx2) - fmaxf(px1,qx1), 0.f);
    float ih = fmaxf(fminf(py2,qy2) - fmaxf(py1,qy1), 0.f);
    float inter = iw * ih;
    float uni = pw*ph + gw*gh - inter + eps;
    float iou = inter / uni;
    float cw = fmaxf(px2,qx2) - fminf(px1,qx1);
    float ch = fmaxf(py2,qy2) - fminf(py1,qy1);
    float ca = cw*ch + eps;
    return iou - (ca - uni) / ca;
}

__global__ __launch_bounds__(256) void k_main(
        const float* __restrict__ p0, const float* __restrict__ p1,
        const float* __restrict__ p2, const float* __restrict__ tg,
        float* __restrict__ out)
{
    const int tid  = threadIdx.x;
    const int lane = tid & 31;
    const int wib  = tid >> 5;

    if (blockIdx.x < OBJ_BLOCKS){
        // ================= dense objectness softplus sum =================
        // warps are level-homogeneous (boundaries at g = 153600, 192000)
        int g = blockIdx.x * 256 + tid;
        float s = 0.f;
        int lev = 2;
        if (g < OBJ_GROUPS){
            int cell = g * 4;
            int base, HW;
            const float* P;
            if (cell < CELLS0){ lev = 0; base = cell;               HW = 6400; P = p0; }
            else if (cell < CELLS0 + CELLS1){ lev = 1; base = cell - CELLS0; HW = 1600; P = p1; }
            else { lev = 2; base = cell - (CELLS0 + CELLS1); HW = 400; P = p2; }
            int n_a = base / HW, hw = base - n_a * HW;
            int n = n_a / 3, a = n_a - n * 3;
            const float4 v = *reinterpret_cast<const float4*>(
                P + (size_t)(n*255 + a*85 + 4) * HW + hw);
            s = sp_(v.x) + sp_(v.y) + sp_(v.z) + sp_(v.w);
        }
        #pragma unroll
        for (int d = 16; d; d >>= 1) s += __shfl_xor_sync(0xffffffffu, s, d);
        __shared__ float sh[8];
        if (lane == 0) sh[wib] = s;
        __syncthreads();
        if (tid == 0){
            float t = sh[0]+sh[1]+sh[2]+sh[3]+sh[4]+sh[5]+sh[6]+sh[7];
            atomicAdd(&g_acc[6 + lev], (double)t);
        }
    } else {
        // ================= candidate path: warp per candidate =============
        // locality remap: cid -> (lev, m, a, off) so one block's 8 warps
        // share 1-2 targets and flagged cells are spatially adjacent.
        int cid = ((blockIdx.x - OBJ_BLOCKS) * 256 + tid) >> 5;
        int lev = cid / CPL;
        int r   = cid - lev * CPL;
        int m   = r / (NA * 5);
        int q   = r - m * (NA * 5);
        int a   = q / 5;
        int off = q - a * 5;

        const int W  = (lev==0) ? 80 : ((lev==1) ? 40 : 20);
        const int HW = W * W;
        const float fW = (float)W;

        float t0 = tg[m*6+0];
        float t1 = tg[m*6+1];
        float tx = tg[m*6+2] * fW;
        float ty = tg[m*6+3] * fW;
        float tw = tg[m*6+4] * fW;
        float th = tg[m*6+5] * fW;

        float aw = c_anch[lev][a][0];
        float ah = c_anch[lev][a][1];
        float rw = aw / tw, rh = ah / th;
        float mr = fmaxf(fmaxf(rw, 1.f/rw), fmaxf(rh, 1.f/rh));
        bool bm = mr < 4.0f;

        float fx = tx - floorf(tx);
        float fy = ty - floorf(ty);
        float ox = 0.f, oy = 0.f;
        bool flag = bm;
        if      (off == 1){ flag = bm && (fx < 0.5f) && (tx > 1.0f);       ox =  0.5f; }
        else if (off == 2){ flag = bm && (fy < 0.5f) && (ty > 1.0f);       oy =  0.5f; }
        else if (off == 3){ flag = bm && (fx > 0.5f) && (tx < fW - 1.0f);  ox = -0.5f; }
        else if (off == 4){ flag = bm && (fy > 0.5f) && (ty < fW - 1.0f);  oy = -0.5f; }

        float lbox_c = 0.f, cls_c = 0.f, corr_c = 0.f;
        int cnt_c = 0, cell_c = -1;

        if (flag){   // warp-uniform
            int gx = (int)floorf(tx - ox);
            int gy = (int)floorf(ty - oy);
            float gox = tx - (float)gx;     // unclamped grid (matches reference)
            float goy = ty - (float)gy;
            int gxc = min(max(gx, 0), W-1);
            int gyc = min(max(gy, 0), W-1);
            int img = min(max((int)t0, 0), NIMG-1);
            int cls = (int)t1;

            const float* P = (lev==0) ? p0 : ((lev==1) ? p1 : p2);
            const float* base = P + (size_t)(img*255 + a*85) * HW + gyc * W + gxc;

            // class logits: lane covers c = lane, lane+32, lane+64
            float s = 0.f, picked = 0.f;
            #pragma unroll
            for (int c = lane; c < NCLS; c += 32){
                float v = __ldg(base + (size_t)(5 + c) * HW);
                s += sp_(v);
                if (c == cls) picked = v;
            }
            // box logits (ch 0..3) + obj logit (ch 4) on lanes 0..4
            float opv = 0.f;
            if (lane < 5) opv = __ldg(base + (size_t)lane * HW);

            #pragma unroll
            for (int d = 16; d; d >>= 1){
                s      += __shfl_xor_sync(0xffffffffu, s, d);
                picked += __shfl_xor_sync(0xffffffffu, picked, d);
            }
            float op0 = __shfl_sync(0xffffffffu, opv, 0);
            float op1 = __shfl_sync(0xffffffffu, opv, 1);
            float op2 = __shfl_sync(0xffffffffu, opv, 2);
            float op3 = __shfl_sync(0xffffffffu, opv, 3);
            float xob = __shfl_sync(0xffffffffu, opv, 4);

            if (lane == 0){
                float px = sig_(op0) * 2.f - 0.5f;
                float py = sig_(op1) * 2.f - 0.5f;
                float sw = sig_(op2) * 2.f;
                float sh2 = sig_(op3) * 2.f;
                float pw = sw * sw * aw;
                float ph = sh2 * sh2 * ah;
                float gi = giou_(px, py, pw, ph, gox, goy, tw, th);
                lbox_c = 1.f - gi;
                cls_c  = s - picked;       // sum_c softplus(x_c) - x_cls
                cnt_c  = 1;
                float ov = fmaxf(gi, 0.f);
                if (ov > 0.f){
                    int lvoff = (lev==0) ? 0 : ((lev==1) ? CELLS0 : (CELLS0+CELLS1));
                    int cell = lvoff + (img*3 + a) * HW + gyc * W + gxc;
                    unsigned old = atomicMax(&g_objmax[cell], __float_as_uint(ov));
                    float oldf = __uint_as_float(old);
                    if (ov > oldf){
                        // telescoping: sum of raises == final max (same x per cell)
                        corr_c = (ov - oldf) * xob;
                        if (old == 0u) cell_c = cell;   // first raiser lists the cell
                        __threadfence();  // publish atomicMax before block's done-mark
                    }
                }
            }
        }

        // ---- block reduction (blocks are level-homogeneous) ----
        __shared__ float sh_lb[8], sh_lc[8], sh_co[8];
        __shared__ int   sh_cn[8], sh_cell[8];
        if (lane == 0){
            sh_lb[wib] = lbox_c; sh_lc[wib] = cls_c; sh_co[wib] = corr_c;
            sh_cn[wib] = cnt_c;  sh_cell[wib] = cell_c;
        }
        __syncthreads();
        if (tid == 0){
            float lb = 0.f, lc = 0.f, co = 0.f; int cn = 0, nv = 0;
            int cells[8];
            #pragma unroll
            for (int i = 0; i < 8; i++){
                lb += sh_lb[i]; lc += sh_lc[i]; co += sh_co[i]; cn += sh_cn[i];
                if (sh_cell[i] >= 0) cells[nv++] = sh_cell[i];
            }
            if (cn){
                atomicAdd(&g_acc[lev],     (double)lb);
                atomicAdd(&g_acc[3 + lev], (double)lc);
                atomicAdd(&g_cnt[lev], cn);
            }
            if (co != 0.f) atomicAdd(&g_acc[9 + lev], (double)co);
            if (nv){
                int bse = atomicAdd(&g_nflag, nv);
                for (int i = 0; i < nv; i++) g_cellList[bse + i] = cells[i];
            }
        }
    }

    // ================= common epilogue: last block finalizes ==============
    __shared__ int s_last, s_n;
    __syncthreads();
    if (tid == 0){
        __threadfence();   // publish this block's g_acc / list writes
        s_last = (atomicAdd(&g_done, 1) == GRID - 1) ? 1 : 0;
        if (s_last) s_n = g_nflag;
    }
    __syncthreads();
    if (s_last){
        // zero every touched g_objmax cell (list-driven, independent stores)
        int n = s_n;
        for (int i = tid; i < n; i += 256) g_objmax[g_cellList[i]] = 0u;

        if (tid == 0){
            const double cells[3] = {614400.0, 153600.0, 38400.0};
            const double bal[3]   = {4.0, 1.0, 0.4};
            double lbox = 0.0, lcls = 0.0, lobj = 0.0;
            #pragma unroll
            for (int l = 0; l < 3; l++){
                double cnt = (g_cnt[l] > 0) ? (double)g_cnt[l] : 1.0;
                lbox += g_acc[l] / cnt;
                lcls += g_acc[3 + l] / (cnt * (double)NCLS);
                lobj += ((g_acc[6 + l] - g_acc[9 + l]) / cells[l]) * bal[l];
            }
            out[0] = (float)((0.05 * lbox + 0.5 * lcls + lobj) * 32.0);
            // reset all state for next graph replay
            #pragma unroll
            for (int j = 0; j < 12; j++) g_acc[j] = 0.0;
            g_cnt[0] = g_cnt[1] = g_cnt[2] = 0;
            g_nflag = 0;
            g_done  = 0;
        }
    }
}

// ---------------------------------------------------------------------------
extern "C" void kernel_launch(void* const* d_in, const int* in_sizes, int n_in,
                              void* d_out, int out_size){
    const float* p0 = (const float*)d_in[0];
    const float* p1 = (const float*)d_in[1];
    const float* p2 = (const float*)d_in[2];
    const float* tg = (const float*)d_in[3];
    float* out = (float*)d_out;
    (void)in_sizes; (void)n_in; (void)out_size;

    k_main<<<GRID, 256>>>(p0, p1, p2, tg, out);
}

// round 5
// speedup vs baseline: 1.0496x; 1.0496x over previous
#include <cuda_runtime.h>

// ---------------------------------------------------------------------------
// ComputeLoss (YOLOv5-style), fixed shapes:
//   p0: (32,255,80,80)  p1: (32,255,40,40)  p2: (32,255,20,20)
//   targets: (1024,6) = [img, cls, cx, cy, w, h]
// Output: one float32 scalar.
//
// SINGLE kernel:
//   blocks [0, OBJ_BLOCKS)      : dense sum of softplus(obj_logit) (3.2 MB stream)
//   blocks [OBJ_BLOCKS, GRID)   : one warp per candidate; GIoU/lbox, lcls,
//                                 telescoping atomicMax correction for lobj
//                                 (NO per-candidate fences: deltas telescope
//                                 through L2's coherent RMW, never re-read)
//   last block to finish        : finalizes scalar, zeroes the touched
//                                 g_objmax cells (compacted list), resets state
// ---------------------------------------------------------------------------

#define NIMG 32
#define NA   3
#define NCLS 80
#define MT   1024
#define CPL  (5*NA*MT)            // 15360 candidates per level
#define TOTC (3*CPL)              // 46080
#define CELLS0 (NIMG*NA*80*80)    // 614400
#define CELLS1 (NIMG*NA*40*40)    // 153600
#define CELLS2 (NIMG*NA*20*20)    // 38400
#define CELLS_TOT (CELLS0+CELLS1+CELLS2)   // 806400

#define OBJ_GROUPS (CELLS_TOT/4)              // 201600 float4 groups
#define OBJ_BLOCKS ((OBJ_GROUPS + 255)/256)   // 788
#define CAND_BLOCKS (TOTC/8)                  // 5760
#define GRID (OBJ_BLOCKS + CAND_BLOCKS)       // 6548

__constant__ float c_anch[3][3][2] = {
  {{1.25f,1.625f},{2.0f,3.75f},{4.125f,2.875f}},
  {{1.875f,3.8125f},{3.875f,2.8125f},{3.6875f,7.4375f}},
  {{3.625f,2.8125f},{4.875f,6.1875f},{11.65625f,10.1875f}}
};

// per-cell objectness max (float bits >= 0). Zero at module load; the last
// block zeroes every touched cell each launch (list-driven).
__device__ unsigned g_objmax[CELLS_TOT];
__device__ int   g_cellList[TOTC];
__device__ int   g_nflag;
__device__ int   g_done;
// [0..2]=lbox, [3..5]=cls, [6..8]=obj_softplus, [9..11]=obj_corr
__device__ double g_acc[12];
__device__ int g_cnt[3];

__device__ __forceinline__ float sp_(float x){          // softplus (fast-math)
    return fmaxf(x, 0.f) + __logf(1.f + __expf(-fabsf(x)));
}
__device__ __forceinline__ float sig_(float x){
    return 1.f / (1.f + __expf(-x));
}

__device__ __forceinline__ float giou_(float px,float py,float pw,float ph,
                                       float gx,float gy,float gw,float gh){
    const float eps = 1e-7f;
    float px1 = px - pw*0.5f, py1 = py - ph*0.5f;
    float px2 = px + pw*0.5f, py2 = py + ph*0.5f;
    float qx1 = gx - gw*0.5f, qy1 = gy - gh*0.5f;
    float qx2 = gx + gw*0.5f, qy2 = gy + gh*0.5f;
    float iw = fmaxf(fminf(px2,qx2) - fmaxf(px1,qx1), 0.f);
    float ih = fmaxf(fminf(py2,qy2) - fmaxf(py1,qy1), 0.f);
    float inter = iw * ih;
    float uni = pw*ph + gw*gh - inter + eps;
    float iou = inter / uni;
    float cw = fmaxf(px2,qx2) - fminf(px1,qx1);
    float ch = fmaxf(py2,qy2) - fminf(py1,qy1);
    float ca = cw*ch + eps;
    return iou - (ca - uni) / ca;
}

__global__ __launch_bounds__(256) void k_main(
        const float* __restrict__ p0, const float* __restrict__ p1,
        const float* __restrict__ p2, const float* __restrict__ tg,
        float* __restrict__ out)
{
    const int tid  = threadIdx.x;
    const int lane = tid & 31;
    const int wib  = tid >> 5;

    if (blockIdx.x < OBJ_BLOCKS){
        // ================= dense objectness softplus sum =================
        // warps are level-homogeneous (boundaries at g = 153600, 192000)
        int g = blockIdx.x * 256 + tid;
        float s = 0.f;
        int lev = 2;
        if (g < OBJ_GROUPS){
            int cell = g * 4;
            int base, HW;
            const float* P;
            if (cell < CELLS0){ lev = 0; base = cell;               HW = 6400; P = p0; }
            else if (cell < CELLS0 + CELLS1){ lev = 1; base = cell - CELLS0; HW = 1600; P = p1; }
            else { lev = 2; base = cell - (CELLS0 + CELLS1); HW = 400; P = p2; }
            int n_a = base / HW, hw = base - n_a * HW;
            int n = n_a / 3, a = n_a - n * 3;
            const float4 v = *reinterpret_cast<const float4*>(
                P + (size_t)(n*255 + a*85 + 4) * HW + hw);
            s = sp_(v.x) + sp_(v.y) + sp_(v.z) + sp_(v.w);
        }
        #pragma unroll
        for (int d = 16; d; d >>= 1) s += __shfl_xor_sync(0xffffffffu, s, d);
        __shared__ float sh[8];
        if (lane == 0) sh[wib] = s;
        __syncthreads();
        if (tid == 0){
            float t = sh[0]+sh[1]+sh[2]+sh[3]+sh[4]+sh[5]+sh[6]+sh[7];
            atomicAdd(&g_acc[6 + lev], (double)t);
        }
    } else {
        // ================= candidate path: warp per candidate =============
        // locality remap: cid -> (lev, m, a, off) so one block's 8 warps
        // share 1-2 targets and flagged cells are spatially adjacent.
        int cid = ((blockIdx.x - OBJ_BLOCKS) * 256 + tid) >> 5;
        int lev = cid / CPL;
        int r   = cid - lev * CPL;
        int m   = r / (NA * 5);
        int q   = r - m * (NA * 5);
        int a   = q / 5;
        int off = q - a * 5;

        const int W  = (lev==0) ? 80 : ((lev==1) ? 40 : 20);
        const int HW = W * W;
        const float fW = (float)W;

        float t0 = tg[m*6+0];
        float t1 = tg[m*6+1];
        float tx = tg[m*6+2] * fW;
        float ty = tg[m*6+3] * fW;
        float tw = tg[m*6+4] * fW;
        float th = tg[m*6+5] * fW;

        float aw = c_anch[lev][a][0];
        float ah = c_anch[lev][a][1];
        float rw = aw / tw, rh = ah / th;
        float mr = fmaxf(fmaxf(rw, 1.f/rw), fmaxf(rh, 1.f/rh));
        bool bm = mr < 4.0f;

        float fx = tx - floorf(tx);
        float fy = ty - floorf(ty);
        float ox = 0.f, oy = 0.f;
        bool flag = bm;
        if      (off == 1){ flag = bm && (fx < 0.5f) && (tx > 1.0f);       ox =  0.5f; }
        else if (off == 2){ flag = bm && (fy < 0.5f) && (ty > 1.0f);       oy =  0.5f; }
        else if (off == 3){ flag = bm && (fx > 0.5f) && (tx < fW - 1.0f);  ox = -0.5f; }
        else if (off == 4){ flag = bm && (fy > 0.5f) && (ty < fW - 1.0f);  oy = -0.5f; }

        float lbox_c = 0.f, cls_c = 0.f, corr_c = 0.f;
        int cnt_c = 0, cell_c = -1;

        if (flag){   // warp-uniform
            int gx = (int)floorf(tx - ox);
            int gy = (int)floorf(ty - oy);
            float gox = tx - (float)gx;     // unclamped grid (matches reference)
            float goy = ty - (float)gy;
            int gxc = min(max(gx, 0), W-1);
            int gyc = min(max(gy, 0), W-1);
            int img = min(max((int)t0, 0), NIMG-1);
            int cls = (int)t1;

            const float* P = (lev==0) ? p0 : ((lev==1) ? p1 : p2);
            const float* base = P + (size_t)(img*255 + a*85) * HW + gyc * W + gxc;

            // class logits: lane covers c = lane, lane+32, lane+64
            float s = 0.f, picked = 0.f;
            #pragma unroll
            for (int c = lane; c < NCLS; c += 32){
                float v = __ldg(base + (size_t)(5 + c) * HW);
                s += sp_(v);
                if (c == cls) picked = v;
            }
            // box logits (ch 0..3) + obj logit (ch 4) on lanes 0..4
            float opv = 0.f;
            if (lane < 5) opv = __ldg(base + (size_t)lane * HW);

            #pragma unroll
            for (int d = 16; d; d >>= 1){
                s      += __shfl_xor_sync(0xffffffffu, s, d);
                picked += __shfl_xor_sync(0xffffffffu, picked, d);
            }
            float op0 = __shfl_sync(0xffffffffu, opv, 0);
            float op1 = __shfl_sync(0xffffffffu, opv, 1);
            float op2 = __shfl_sync(0xffffffffu, opv, 2);
            float op3 = __shfl_sync(0xffffffffu, opv, 3);
            float xob = __shfl_sync(0xffffffffu, opv, 4);

            if (lane == 0){
                float px = sig_(op0) * 2.f - 0.5f;
                float py = sig_(op1) * 2.f - 0.5f;
                float sw = sig_(op2) * 2.f;
                float sh2 = sig_(op3) * 2.f;
                float pw = sw * sw * aw;
                float ph = sh2 * sh2 * ah;
                float gi = giou_(px, py, pw, ph, gox, goy, tw, th);
                lbox_c = 1.f - gi;
                cls_c  = s - picked;       // sum_c softplus(x_c) - x_cls
                cnt_c  = 1;
                float ov = fmaxf(gi, 0.f);
                if (ov > 0.f){
                    int lvoff = (lev==0) ? 0 : ((lev==1) ? CELLS0 : (CELLS0+CELLS1));
                    int cell = lvoff + (img*3 + a) * HW + gyc * W + gxc;
                    unsigned old = atomicMax(&g_objmax[cell], __float_as_uint(ov));
                    float oldf = __uint_as_float(old);
                    if (ov > oldf){
                        // telescoping: sum of successful raises == final max
                        // (x identical for all candidates of a cell). The
                        // atomic itself serializes at L2 — NO fence needed,
                        // g_objmax is never re-read.
                        corr_c = (ov - oldf) * xob;
                        if (old == 0u) cell_c = cell;   // first raiser lists cell
                    }
                }
            }
        }

        // ---- block reduction (blocks are level-homogeneous) ----
        __shared__ float sh_lb[8], sh_lc[8], sh_co[8];
        __shared__ int   sh_cn[8], sh_cell[8];
        if (lane == 0){
            sh_lb[wib] = lbox_c; sh_lc[wib] = cls_c; sh_co[wib] = corr_c;
            sh_cn[wib] = cnt_c;  sh_cell[wib] = cell_c;
        }
        __syncthreads();
        if (tid == 0){
            float lb = 0.f, lc = 0.f, co = 0.f; int cn = 0, nv = 0;
            int cells[8];
            #pragma unroll
            for (int i = 0; i < 8; i++){
                lb += sh_lb[i]; lc += sh_lc[i]; co += sh_co[i]; cn += sh_cn[i];
                if (sh_cell[i] >= 0) cells[nv++] = sh_cell[i];
            }
            if (cn){
                atomicAdd(&g_acc[lev],     (double)lb);
                atomicAdd(&g_acc[3 + lev], (double)lc);
                atomicAdd(&g_cnt[lev], cn);
            }
            if (co != 0.f) atomicAdd(&g_acc[9 + lev], (double)co);
            if (nv){
                int bse = atomicAdd(&g_nflag, nv);
                for (int i = 0; i < nv; i++) g_cellList[bse + i] = cells[i];
            }
        }
    }

    // ================= common epilogue: last block finalizes ==============
    __shared__ int s_last, s_n;
    __syncthreads();
    if (tid == 0){
        __threadfence();   // publish this block's g_cellList / g_acc writes
        s_last = (atomicAdd(&g_done, 1) == GRID - 1) ? 1 : 0;
        if (s_last) s_n = g_nflag;
    }
    __syncthreads();
    if (s_last){
        // zero every touched g_objmax cell (list-driven, independent stores)
        int n = s_n;
        for (int i = tid; i < n; i += 256) g_objmax[g_cellList[i]] = 0u;

        if (tid == 0){
            const double cells[3] = {614400.0, 153600.0, 38400.0};
            const double bal[3]   = {4.0, 1.0, 0.4};
            double lbox = 0.0, lcls = 0.0, lobj = 0.0;
            #pragma unroll
            for (int l = 0; l < 3; l++){
                double cnt = (g_cnt[l] > 0) ? (double)g_cnt[l] : 1.0;
                lbox += g_acc[l] / cnt;
                lcls += g_acc[3 + l] / (cnt * (double)NCLS);
                lobj += ((g_acc[6 + l] - g_acc[9 + l]) / cells[l]) * bal[l];
            }
            out[0] = (float)((0.05 * lbox + 0.5 * lcls + lobj) * 32.0);
            // reset all state for next graph replay
            #pragma unroll
            for (int j = 0; j < 12; j++) g_acc[j] = 0.0;
            g_cnt[0] = g_cnt[1] = g_cnt[2] = 0;
            g_nflag = 0;
            g_done  = 0;
        }
    }
}

// ---------------------------------------------------------------------------
extern "C" void kernel_launch(void* const* d_in, const int* in_sizes, int n_in,
                              void* d_out, int out_size){
    const float* p0 = (const float*)d_in[0];
    const float* p1 = (const float*)d_in[1];
    const float* p2 = (const float*)d_in[2];
    const float* tg = (const float*)d_in[3];
    float* out = (float*)d_out;
    (void)in_sizes; (void)n_in; (void)out_size;

    k_main<<<GRID, 256>>>(p0, p1, p2, tg, out);
}